// round 1
// baseline (speedup 1.0000x reference)
#include <cuda_runtime.h>
#include <math.h>

// Problem constants (fixed by the reference setup)
#define NTOK   8192       // B*S
#define EDIM   768
#define SEQ    256
#define NB     32
#define NH     12
#define HDIM   64
#define FFDIM  2048
#define E3     2304       // 3*E

// -------------------- scratch (no cudaMalloc allowed) --------------------
__device__ float g_X  [NTOK * EDIM];   // residual stream
__device__ float g_Yb [NTOK * EDIM];   // GEMM outputs / LN(x) staging
__device__ float g_QKV[NTOK * E3];     // qkv projection
__device__ float g_O  [NTOK * EDIM];   // attention out / dense out
__device__ float g_F  [NTOK * FFDIM];  // FFN intermediate
__device__ float g_C  [NTOK];          // cosine per token

// -------------------- block reduction helper (256 threads) --------------------
__device__ __forceinline__ float block_sum256(float v, volatile float* red) {
    #pragma unroll
    for (int o = 16; o > 0; o >>= 1) v += __shfl_xor_sync(0xffffffffu, v, o);
    const int w = threadIdx.x >> 5;
    __syncthreads();                       // protect red[] reuse across calls
    if ((threadIdx.x & 31) == 0) red[w] = v;
    __syncthreads();
    return red[0] + red[1] + red[2] + red[3] + red[4] + red[5] + red[6] + red[7];
}

// -------------------- embed + LN --------------------
__global__ void __launch_bounds__(256) embed_ln_kernel(
    const float* __restrict__ tok, const int* __restrict__ pos, const int* __restrict__ typ,
    const float* __restrict__ pe, const float* __restrict__ temb,
    const float* __restrict__ w, const float* __restrict__ bb, float* __restrict__ X)
{
    __shared__ float red[8];
    const int t = blockIdx.x, tid = threadIdx.x;
    const float* tr = tok  + (size_t)t * EDIM;
    const float* pr = pe   + (size_t)pos[t] * EDIM;
    const float* yr = temb + (size_t)typ[t] * EDIM;
    float v[3];
    #pragma unroll
    for (int i = 0; i < 3; i++) { int c = tid + i * 256; v[i] = tr[c] + pr[c] + yr[c]; }
    float m = block_sum256(v[0] + v[1] + v[2], red) * (1.0f / 768.0f);
    float q = 0.f;
    #pragma unroll
    for (int i = 0; i < 3; i++) { float d = v[i] - m; q += d * d; }
    q = block_sum256(q, red);
    float inv = rsqrtf(q * (1.0f / 768.0f) + 1e-5f);
    #pragma unroll
    for (int i = 0; i < 3; i++) {
        int c = tid + i * 256;
        X[(size_t)t * EDIM + c] = (v[i] - m) * inv * w[c] + bb[c];
    }
}

// -------------------- (optional residual) + LN --------------------
template<bool ADD>
__global__ void __launch_bounds__(256) addln_kernel(
    const float* __restrict__ Xin, const float* __restrict__ Y,
    const float* __restrict__ w, const float* __restrict__ bb, float* __restrict__ Xout)
{
    __shared__ float red[8];
    const int t = blockIdx.x, tid = threadIdx.x;
    float v[3];
    #pragma unroll
    for (int i = 0; i < 3; i++) {
        int c = tid + i * 256;
        float x = Xin[(size_t)t * EDIM + c];
        if (ADD) x += Y[(size_t)t * EDIM + c];
        v[i] = x;
    }
    float m = block_sum256(v[0] + v[1] + v[2], red) * (1.0f / 768.0f);
    float q = 0.f;
    #pragma unroll
    for (int i = 0; i < 3; i++) { float d = v[i] - m; q += d * d; }
    q = block_sum256(q, red);
    float inv = rsqrtf(q * (1.0f / 768.0f) + 1e-5f);
    #pragma unroll
    for (int i = 0; i < 3; i++) {
        int c = tid + i * 256;
        Xout[(size_t)t * EDIM + c] = (v[i] - m) * inv * w[c] + bb[c];
    }
}

// -------------------- generic SGEMM: C[M,N] = A[M,K] @ B[N,K]^T + bias, ACT --------------------
// BM=BN=128, BK=8, 256 threads, 8x8 micro-tile. All dims multiples of 128/8 here.
template<int ACT>  // 0=none, 1=relu, 2=tanh
__global__ void __launch_bounds__(256) sgemm_kernel(
    const float* __restrict__ A, const float* __restrict__ B,
    const float* __restrict__ bias, float* __restrict__ C,
    int M, int N, int K)
{
    __shared__ float As[8][128];
    __shared__ float Bs[8][128];
    const int tid  = threadIdx.x;
    const int lrow = tid >> 1;
    const int lcol = (tid & 1) << 2;
    const int tx   = tid & 15;
    const int ty   = tid >> 4;
    const float* Ab = A + (size_t)blockIdx.y * 128 * K;
    const float* Bb = B + (size_t)blockIdx.x * 128 * K;

    float acc[8][8];
    #pragma unroll
    for (int i = 0; i < 8; i++)
        #pragma unroll
        for (int j = 0; j < 8; j++) acc[i][j] = 0.f;

    for (int k0 = 0; k0 < K; k0 += 8) {
        float4 av = *(const float4*)(Ab + (size_t)lrow * K + k0 + lcol);
        float4 bv = *(const float4*)(Bb + (size_t)lrow * K + k0 + lcol);
        __syncthreads();
        As[lcol + 0][lrow] = av.x; As[lcol + 1][lrow] = av.y;
        As[lcol + 2][lrow] = av.z; As[lcol + 3][lrow] = av.w;
        Bs[lcol + 0][lrow] = bv.x; Bs[lcol + 1][lrow] = bv.y;
        Bs[lcol + 2][lrow] = bv.z; Bs[lcol + 3][lrow] = bv.w;
        __syncthreads();
        #pragma unroll
        for (int k = 0; k < 8; k++) {
            float ar[8], br[8];
            *(float4*)&ar[0] = *(const float4*)&As[k][ty * 4];
            *(float4*)&ar[4] = *(const float4*)&As[k][64 + ty * 4];
            *(float4*)&br[0] = *(const float4*)&Bs[k][tx * 4];
            *(float4*)&br[4] = *(const float4*)&Bs[k][64 + tx * 4];
            #pragma unroll
            for (int i = 0; i < 8; i++)
                #pragma unroll
                for (int j = 0; j < 8; j++)
                    acc[i][j] += ar[i] * br[j];
        }
    }

    #pragma unroll
    for (int i = 0; i < 8; i++) {
        int m = blockIdx.y * 128 + ((i < 4) ? (ty * 4 + i) : (64 + ty * 4 + i - 4));
        #pragma unroll
        for (int j = 0; j < 8; j++) {
            int n = blockIdx.x * 128 + ((j < 4) ? (tx * 4 + j) : (64 + tx * 4 + j - 4));
            float v = acc[i][j] + bias[n];
            if (ACT == 1) v = fmaxf(v, 0.f);
            if (ACT == 2) v = tanhf(v);
            C[(size_t)m * N + n] = v;
        }
    }
}

// -------------------- fused attention per (b,h,qtile) --------------------
// Whole K/V head (256x64 each) + Q tile (64x64) in dynamic smem (144 KB).
// mask is all-false by construction -> unmasked softmax.
__global__ void __launch_bounds__(256) attn_kernel(
    const float* __restrict__ qkv, float* __restrict__ obuf)
{
    extern __shared__ float sm[];
    float* Vs = sm;                 // [256][64]
    float* Qt = sm + 256 * 64;      // [64][64]  k-major: Qt[d][q]
    float* Kt = Qt + 64 * 64;       // [64][256] k-major: Kt[d][key]
    float* St = sm + 256 * 64;      // [256][68] scores/probs, overlaps Qt/Kt after GEMM1

    const int tid   = threadIdx.x;
    const int qtile = blockIdx.x;             // 0..3 (64 q rows each)
    const int bh    = blockIdx.y;             // 0..383
    const int b = bh / NH, h = bh % NH;
    const float* base = qkv + (size_t)b * SEQ * E3 + h * HDIM;

    // load K (transposed), V (natural), Q (transposed)
    #pragma unroll
    for (int i = 0; i < 16; i++) {
        int idx = tid + i * 256;              // 0..4095
        int row = idx >> 4;
        int c4  = (idx & 15) << 2;
        float4 kv = *(const float4*)(base + (size_t)row * E3 + EDIM     + c4);
        float4 vv = *(const float4*)(base + (size_t)row * E3 + 2 * EDIM + c4);
        *(float4*)&Vs[row * 64 + c4] = vv;
        Kt[(c4 + 0) * 256 + row] = kv.x; Kt[(c4 + 1) * 256 + row] = kv.y;
        Kt[(c4 + 2) * 256 + row] = kv.z; Kt[(c4 + 3) * 256 + row] = kv.w;
    }
    #pragma unroll
    for (int i = 0; i < 4; i++) {
        int idx = tid + i * 256;              // 0..1023
        int row = idx >> 4;
        int c4  = (idx & 15) << 2;
        float4 qv = *(const float4*)(base + (size_t)(qtile * 64 + row) * E3 + c4);
        Qt[(c4 + 0) * 64 + row] = qv.x; Qt[(c4 + 1) * 64 + row] = qv.y;
        Qt[(c4 + 2) * 64 + row] = qv.z; Qt[(c4 + 3) * 64 + row] = qv.w;
    }
    __syncthreads();

    // GEMM1: S[q,key] = Q . K / 8    (8 ty x 32 tx threads, 8x8 micro)
    {
        const int tx = tid & 31, ty = tid >> 5;
        float acc[8][8];
        #pragma unroll
        for (int i = 0; i < 8; i++)
            #pragma unroll
            for (int j = 0; j < 8; j++) acc[i][j] = 0.f;
        for (int k = 0; k < 64; k++) {
            float ar[8], br[8];
            *(float4*)&ar[0] = *(const float4*)&Qt[k * 64  + ty * 8];
            *(float4*)&ar[4] = *(const float4*)&Qt[k * 64  + ty * 8 + 4];
            *(float4*)&br[0] = *(const float4*)&Kt[k * 256 + tx * 8];
            *(float4*)&br[4] = *(const float4*)&Kt[k * 256 + tx * 8 + 4];
            #pragma unroll
            for (int i = 0; i < 8; i++)
                #pragma unroll
                for (int j = 0; j < 8; j++)
                    acc[i][j] += ar[i] * br[j];
        }
        __syncthreads();   // Qt/Kt reads done before St overwrites them
        #pragma unroll
        for (int j = 0; j < 8; j++)
            #pragma unroll
            for (int i = 0; i < 8; i++)
                St[(tx * 8 + j) * 68 + ty * 8 + i] = acc[i][j] * 0.125f;
    }
    __syncthreads();

    // softmax over key (column q of St), 4 threads per q row
    {
        const int q = tid >> 2, part = tid & 3;
        float mx = -1e30f;
        for (int j = 0; j < 64; j++) mx = fmaxf(mx, St[(part * 64 + j) * 68 + q]);
        mx = fmaxf(mx, __shfl_xor_sync(0xffffffffu, mx, 1));
        mx = fmaxf(mx, __shfl_xor_sync(0xffffffffu, mx, 2));
        float ssum = 0.f;
        for (int j = 0; j < 64; j++) ssum += expf(St[(part * 64 + j) * 68 + q] - mx);
        ssum += __shfl_xor_sync(0xffffffffu, ssum, 1);
        ssum += __shfl_xor_sync(0xffffffffu, ssum, 2);
        float inv = 1.0f / ssum;
        for (int j = 0; j < 64; j++) {
            int r = part * 64 + j;
            St[r * 68 + q] = expf(St[r * 68 + q] - mx) * inv;
        }
    }
    __syncthreads();

    // GEMM2: O[q,d] = P @ V   (16x16 threads, 4x4 micro)
    {
        const int tx = tid & 15, ty = tid >> 4;
        float acc[4][4];
        #pragma unroll
        for (int i = 0; i < 4; i++)
            #pragma unroll
            for (int j = 0; j < 4; j++) acc[i][j] = 0.f;
        for (int k = 0; k < 256; k++) {
            float4 a  = *(const float4*)&St[k * 68 + ty * 4];
            float4 bv = *(const float4*)&Vs[k * 64 + tx * 4];
            float ar[4] = {a.x, a.y, a.z, a.w};
            float br[4] = {bv.x, bv.y, bv.z, bv.w};
            #pragma unroll
            for (int i = 0; i < 4; i++)
                #pragma unroll
                for (int j = 0; j < 4; j++)
                    acc[i][j] += ar[i] * br[j];
        }
        #pragma unroll
        for (int i = 0; i < 4; i++) {
            int t = b * SEQ + qtile * 64 + ty * 4 + i;
            #pragma unroll
            for (int j = 0; j < 4; j++)
                obuf[(size_t)t * EDIM + h * HDIM + tx * 4 + j] = acc[i][j];
        }
    }
}

// -------------------- cosine(token_embeds, out) per token --------------------
__global__ void __launch_bounds__(256) cos_kernel(
    const float* __restrict__ tok, const float* __restrict__ out, float* __restrict__ cosb)
{
    const int t = blockIdx.x * 8 + (threadIdx.x >> 5);
    const int l = threadIdx.x & 31;
    const float* a = tok + (size_t)t * EDIM;
    const float* b = out + (size_t)t * EDIM;
    float dot = 0.f, na = 0.f, nb = 0.f;
    for (int i = l; i < EDIM; i += 32) {
        float x = a[i], y = b[i];
        dot += x * y; na += x * x; nb += y * y;
    }
    #pragma unroll
    for (int o = 16; o > 0; o >>= 1) {
        dot += __shfl_xor_sync(0xffffffffu, dot, o);
        na  += __shfl_xor_sync(0xffffffffu, na,  o);
        nb  += __shfl_xor_sync(0xffffffffu, nb,  o);
    }
    if (l == 0)
        cosb[t] = dot / fmaxf(sqrtf(na) * sqrtf(nb), 1e-8f);
}

// -------------------- masked softmax + gumbel top-k -> 0/1 mask --------------------
// KEEP_HIST=64 of 128 type-1 positions; KEEP_TGT=63 of 127 type-2 positions.
// Forward value of the straight-through estimator is y_hard (exact at zeros).
__global__ void __launch_bounds__(256) topk_kernel(
    const float* __restrict__ cosb, const float* __restrict__ gh, const float* __restrict__ gt,
    const int* __restrict__ typ, float* __restrict__ out)
{
    __shared__ float red[8];
    __shared__ float glh[256], glt[256];
    const int b = blockIdx.x, s = threadIdx.x;
    const int idx = b * SEQ + s;
    const int t = typ[idx];
    const float c = cosb[idx];
    const bool vh = (t == 1), vt = (t == 2);
    float eh = vh ? expf(c) : 0.f;
    float et = vt ? expf(c) : 0.f;
    float Zh = block_sum256(eh, red);
    float Zt = block_sum256(et, red);
    // hist: gl = log(exp(c)/Zh) + g   (TAU = 1)
    glh[s] = vh ? (logf(eh / Zh) + gh[idx]) : -1e30f;
    // tgt (training): gl = log(1 - exp(c)/Zt) + g
    glt[s] = vt ? (logf(1.0f - et / Zt) + gt[idx]) : -1e30f;
    __syncthreads();
    int ch = 0, ct = 0;
    const float mh = glh[s], mt = glt[s];
    for (int j = 0; j < 256; j++) {
        float a = glh[j], d = glt[j];
        ch += (a > mh) || (a == mh && j < s);   // top_k tie-break: lower index wins
        ct += (d > mt) || (d == mt && j < s);
    }
    float r = 0.f;
    if (vh && ch < 64) r += 1.0f;
    if (vt && ct < 63) r += 1.0f;
    out[idx] = r;
}

// -------------------- host orchestration (graph-capturable) --------------------
extern "C" void kernel_launch(void* const* d_in, const int* in_sizes, int n_in,
                              void* d_out, int out_size)
{
    const float* tok  = (const float*)d_in[0];
    // d_in[1] = attention_mask: all-false by construction -> unused
    const int*   pos  = (const int*)  d_in[2];
    const int*   typ  = (const int*)  d_in[3];
    const float* gh   = (const float*)d_in[4];
    const float* gt   = (const float*)d_in[5];
    const float* pe   = (const float*)d_in[6];
    const float* temb = (const float*)d_in[7];
    const float* lnw  = (const float*)d_in[8];
    const float* lnb  = (const float*)d_in[9];
    const float* dw   = (const float*)d_in[10];
    const float* db   = (const float*)d_in[11];
    const float* qkvw = (const float*)d_in[12];
    const float* qkvb = (const float*)d_in[13];
    const float* ow   = (const float*)d_in[14];
    const float* obv  = (const float*)d_in[15];
    const float* ln1w = (const float*)d_in[16];
    const float* ln1b = (const float*)d_in[17];
    const float* l1w  = (const float*)d_in[18];
    const float* l1b  = (const float*)d_in[19];
    const float* l2w  = (const float*)d_in[20];
    const float* l2b  = (const float*)d_in[21];
    const float* ln2w = (const float*)d_in[22];
    const float* ln2b = (const float*)d_in[23];

    float *X, *Y, *QKV, *O, *F, *C;
    cudaGetSymbolAddress((void**)&X,   g_X);
    cudaGetSymbolAddress((void**)&Y,   g_Yb);
    cudaGetSymbolAddress((void**)&QKV, g_QKV);
    cudaGetSymbolAddress((void**)&O,   g_O);
    cudaGetSymbolAddress((void**)&F,   g_F);
    cudaGetSymbolAddress((void**)&C,   g_C);

    const int ATTN_SMEM = (256 * 64 + 64 * 64 + 64 * 256) * 4;  // 147456 B
    cudaFuncSetAttribute(attn_kernel, cudaFuncAttributeMaxDynamicSharedMemorySize, ATTN_SMEM);

    embed_ln_kernel<<<NTOK, 256>>>(tok, pos, typ, pe, temb, lnw, lnb, X);

    for (int l = 0; l < 2; l++) {
        sgemm_kernel<0><<<dim3(E3 / 128, NTOK / 128), 256>>>(
            X, qkvw + (size_t)l * E3 * EDIM, qkvb + (size_t)l * E3, QKV, NTOK, E3, EDIM);
        attn_kernel<<<dim3(4, NB * NH), 256, ATTN_SMEM>>>(QKV, O);
        sgemm_kernel<0><<<dim3(EDIM / 128, NTOK / 128), 256>>>(
            O, ow + (size_t)l * EDIM * EDIM, obv + (size_t)l * EDIM, Y, NTOK, EDIM, EDIM);
        addln_kernel<true><<<NTOK, 256>>>(X, Y, ln1w + (size_t)l * EDIM, ln1b + (size_t)l * EDIM, X);
        sgemm_kernel<1><<<dim3(FFDIM / 128, NTOK / 128), 256>>>(
            X, l1w + (size_t)l * FFDIM * EDIM, l1b + (size_t)l * FFDIM, F, NTOK, FFDIM, EDIM);
        sgemm_kernel<0><<<dim3(EDIM / 128, NTOK / 128), 256>>>(
            F, l2w + (size_t)l * EDIM * FFDIM, l2b + (size_t)l * EDIM, Y, NTOK, EDIM, FFDIM);
        addln_kernel<true><<<NTOK, 256>>>(X, Y, ln2w + (size_t)l * EDIM, ln2b + (size_t)l * EDIM, X);
    }

    addln_kernel<false><<<NTOK, 256>>>(X, nullptr, lnw, lnb, Y);     // final LN
    sgemm_kernel<2><<<dim3(EDIM / 128, NTOK / 128), 256>>>(          // tanh(dense)
        Y, dw, db, O, NTOK, EDIM, EDIM);
    cos_kernel<<<NTOK / 8, 256>>>(tok, O, C);
    topk_kernel<<<NB, 256>>>(C, gh, gt, typ, (float*)d_out);
}

// round 3
// speedup vs baseline: 2.1900x; 2.1900x over previous
#include <cuda_runtime.h>
#include <cuda_bf16.h>
#include <math.h>
#include <stdint.h>

// Problem constants
#define NTOK   8192
#define EDIM   768
#define SEQ    256
#define NB     32
#define NH     12
#define HDIM   64
#define FFDIM  2048
#define E3     2304

// -------------------- scratch --------------------
__device__ float g_X  [NTOK * EDIM];
__device__ float g_Yb [NTOK * EDIM];
__device__ float g_QKV[NTOK * E3];
__device__ float g_O  [NTOK * EDIM];
__device__ float g_C  [NTOK];

__device__ __nv_bfloat16 g_Ah[NTOK * EDIM],  g_Al[NTOK * EDIM];
__device__ __nv_bfloat16 g_Fh[NTOK * FFDIM], g_Fl[NTOK * FFDIM];
__device__ __nv_bfloat16 g_Wqkv_h[2 * E3 * EDIM],   g_Wqkv_l[2 * E3 * EDIM];
__device__ __nv_bfloat16 g_Wout_h[2 * EDIM * EDIM], g_Wout_l[2 * EDIM * EDIM];
__device__ __nv_bfloat16 g_W1_h[2 * FFDIM * EDIM],  g_W1_l[2 * FFDIM * EDIM];
__device__ __nv_bfloat16 g_W2_h[2 * EDIM * FFDIM],  g_W2_l[2 * EDIM * FFDIM];
__device__ __nv_bfloat16 g_Wd_h[EDIM * EDIM],       g_Wd_l[EDIM * EDIM];

// -------------------- helpers --------------------
__device__ __forceinline__ uint32_t smem_u32(const void* p) {
    uint32_t a;
    asm("{ .reg .u64 t; cvta.to.shared.u64 t, %1; cvt.u32.u64 %0, t; }" : "=r"(a) : "l"(p));
    return a;
}
__device__ __forceinline__ void split_bf16(float v, __nv_bfloat16& h, __nv_bfloat16& l) {
    h = __float2bfloat16(v);
    l = __float2bfloat16(v - __bfloat162float(h));
}

#define CP_ASYNC16(saddr, gptr) \
    asm volatile("cp.async.cg.shared.global [%0], [%1], 16;" :: "r"(saddr), "l"(gptr))
#define CP_COMMIT() asm volatile("cp.async.commit_group;" ::: "memory")
#define CP_WAIT2()  asm volatile("cp.async.wait_group 2;" ::: "memory")
#define CP_WAIT0()  asm volatile("cp.async.wait_group 0;" ::: "memory")

#define LDSM4(r, addr) \
    asm volatile("ldmatrix.sync.aligned.m8n8.x4.shared.b16 {%0,%1,%2,%3}, [%4];" \
        : "=r"((r)[0]), "=r"((r)[1]), "=r"((r)[2]), "=r"((r)[3]) : "r"(addr))

#define MMA_BF16(c, a, b) \
    asm volatile("mma.sync.aligned.m16n8k16.row.col.f32.bf16.bf16.f32 " \
        "{%0,%1,%2,%3}, {%4,%5,%6,%7}, {%8,%9}, {%0,%1,%2,%3};" \
        : "+f"((c)[0]), "+f"((c)[1]), "+f"((c)[2]), "+f"((c)[3]) \
        : "r"((a)[0]), "r"((a)[1]), "r"((a)[2]), "r"((a)[3]), "r"((b)[0]), "r"((b)[1]))

// -------------------- block reduction (256 threads) --------------------
__device__ __forceinline__ float block_sum256(float v, volatile float* red) {
    #pragma unroll
    for (int o = 16; o > 0; o >>= 1) v += __shfl_xor_sync(0xffffffffu, v, o);
    const int w = threadIdx.x >> 5;
    __syncthreads();
    if ((threadIdx.x & 31) == 0) red[w] = v;
    __syncthreads();
    return red[0] + red[1] + red[2] + red[3] + red[4] + red[5] + red[6] + red[7];
}

// -------------------- fp32 -> (hi,lo) bf16 converter --------------------
__global__ void __launch_bounds__(256) cvt_kernel(
    const float* __restrict__ s, __nv_bfloat16* __restrict__ hi,
    __nv_bfloat16* __restrict__ lo, int n4)
{
    int i = blockIdx.x * 256 + threadIdx.x;
    const int stride = gridDim.x * 256;
    for (; i < n4; i += stride) {
        float4 v = ((const float4*)s)[i];
        union { __nv_bfloat16 b[4]; uint2 u; } ph, pl;
        split_bf16(v.x, ph.b[0], pl.b[0]);
        split_bf16(v.y, ph.b[1], pl.b[1]);
        split_bf16(v.z, ph.b[2], pl.b[2]);
        split_bf16(v.w, ph.b[3], pl.b[3]);
        ((uint2*)hi)[i] = ph.u;
        ((uint2*)lo)[i] = pl.u;
    }
}

// -------------------- embed + LN (fp32 X + hi/lo split) --------------------
__global__ void __launch_bounds__(256) embed_ln_kernel(
    const float* __restrict__ tok, const int* __restrict__ pos, const int* __restrict__ typ,
    const float* __restrict__ pe, const float* __restrict__ temb,
    const float* __restrict__ w, const float* __restrict__ bb, float* __restrict__ X,
    __nv_bfloat16* __restrict__ Xh, __nv_bfloat16* __restrict__ Xl)
{
    __shared__ float red[8];
    const int t = blockIdx.x, tid = threadIdx.x;
    const float* tr = tok  + (size_t)t * EDIM;
    const float* pr = pe   + (size_t)pos[t] * EDIM;
    const float* yr = temb + (size_t)typ[t] * EDIM;
    float v[3];
    #pragma unroll
    for (int i = 0; i < 3; i++) { int c = tid + i * 256; v[i] = tr[c] + pr[c] + yr[c]; }
    float m = block_sum256(v[0] + v[1] + v[2], red) * (1.0f / 768.0f);
    float q = 0.f;
    #pragma unroll
    for (int i = 0; i < 3; i++) { float d = v[i] - m; q += d * d; }
    q = block_sum256(q, red);
    float inv = rsqrtf(q * (1.0f / 768.0f) + 1e-5f);
    #pragma unroll
    for (int i = 0; i < 3; i++) {
        int c = tid + i * 256;
        float o = (v[i] - m) * inv * w[c] + bb[c];
        X[(size_t)t * EDIM + c] = o;
        __nv_bfloat16 h, l; split_bf16(o, h, l);
        Xh[(size_t)t * EDIM + c] = h;
        Xl[(size_t)t * EDIM + c] = l;
    }
}

// -------------------- residual + LN (fp32 X + hi/lo split) --------------------
template<bool ADD>
__global__ void __launch_bounds__(256) addln_kernel(
    const float* __restrict__ Xin, const float* __restrict__ Y,
    const float* __restrict__ w, const float* __restrict__ bb, float* __restrict__ Xout,
    __nv_bfloat16* __restrict__ Xh, __nv_bfloat16* __restrict__ Xl)
{
    __shared__ float red[8];
    const int t = blockIdx.x, tid = threadIdx.x;
    float v[3];
    #pragma unroll
    for (int i = 0; i < 3; i++) {
        int c = tid + i * 256;
        float x = Xin[(size_t)t * EDIM + c];
        if (ADD) x += Y[(size_t)t * EDIM + c];
        v[i] = x;
    }
    float m = block_sum256(v[0] + v[1] + v[2], red) * (1.0f / 768.0f);
    float q = 0.f;
    #pragma unroll
    for (int i = 0; i < 3; i++) { float d = v[i] - m; q += d * d; }
    q = block_sum256(q, red);
    float inv = rsqrtf(q * (1.0f / 768.0f) + 1e-5f);
    #pragma unroll
    for (int i = 0; i < 3; i++) {
        int c = tid + i * 256;
        float o = (v[i] - m) * inv * w[c] + bb[c];
        Xout[(size_t)t * EDIM + c] = o;
        __nv_bfloat16 h, l; split_bf16(o, h, l);
        Xh[(size_t)t * EDIM + c] = h;
        Xl[(size_t)t * EDIM + c] = l;
    }
}

// -------------------- mma.sync split-bf16 GEMM --------------------
// C[M,N] = A[M,K] @ B[N,K]^T + bias via AhBh + AhBl + AlBh (bf16x3 ~ fp32).
// 128x128 tile, BK=32, 4-stage cp.async, 8 warps (2m x 4n), warp tile 64x32.
// Smem stage: Ah[8K] Al[8K] Bh[8K] Bl[8K] = 32KB; 4 stages = 128KB.
// Swizzle: 64B rows of 4x16B chunks, chunk' = chunk ^ ((row>>1)&3).
#define TG_SMEM (4 * 32768)

__device__ __forceinline__ void tg_load_stage(
    uint32_t sb, const __nv_bfloat16* __restrict__ Ahb, const __nv_bfloat16* __restrict__ Alb,
    const __nv_bfloat16* __restrict__ Bhb, const __nv_bfloat16* __restrict__ Blb,
    int K, int kc, int tid)
{
    #pragma unroll
    for (int t = 0; t < 2; t++) {
        int idx = tid + t * 256;          // 0..511
        int row = idx >> 2;               // 0..127
        int ch  = idx & 3;
        uint32_t soff = (uint32_t)(row * 64 + ((ch ^ ((row >> 1) & 3)) << 4));
        size_t goff = (size_t)row * K + kc + ch * 8;
        CP_ASYNC16(sb +         soff, Ahb + goff);
        CP_ASYNC16(sb +  8192 + soff, Alb + goff);
        CP_ASYNC16(sb + 16384 + soff, Bhb + goff);
        CP_ASYNC16(sb + 24576 + soff, Blb + goff);
    }
}

template<int ACT, int OSPLIT>   // ACT: 0=none 1=relu 2=tanh; OSPLIT: 0 fp32 C, 1 bf16 hi/lo
__global__ void __launch_bounds__(256) tgemm_kernel(
    const __nv_bfloat16* __restrict__ Ah, const __nv_bfloat16* __restrict__ Al,
    const __nv_bfloat16* __restrict__ Bh, const __nv_bfloat16* __restrict__ Bl,
    const float* __restrict__ bias, float* __restrict__ C,
    __nv_bfloat16* __restrict__ Chi, __nv_bfloat16* __restrict__ Clo,
    int M, int N, int K)
{
    extern __shared__ __align__(128) unsigned char dsm[];
    const uint32_t sbase = smem_u32(dsm);
    const int tid = threadIdx.x;
    const int w = tid >> 5, l = tid & 31;
    const int warp_m = w & 1;             // 0..1 (64 rows each)
    const int warp_n = w >> 1;            // 0..3 (32 cols each)
    const int NC = K >> 5;

    const __nv_bfloat16* Ahb = Ah + (size_t)blockIdx.y * 128 * K;
    const __nv_bfloat16* Alb = Al + (size_t)blockIdx.y * 128 * K;
    const __nv_bfloat16* Bhb = Bh + (size_t)blockIdx.x * 128 * K;
    const __nv_bfloat16* Blb = Bl + (size_t)blockIdx.x * 128 * K;

    // prologue: 3 stages in flight
    #pragma unroll
    for (int s = 0; s < 3; s++) {
        tg_load_stage(sbase + s * 32768, Ahb, Alb, Bhb, Blb, K, s * 32, tid);
        CP_COMMIT();
    }

    float acc[4][4][4];
    #pragma unroll
    for (int im = 0; im < 4; im++)
        #pragma unroll
        for (int in = 0; in < 4; in++)
            #pragma unroll
            for (int r = 0; r < 4; r++) acc[im][in][r] = 0.f;

    // per-thread ldmatrix lane addressing
    const int arow = ((l >> 3) & 1) * 8 + (l & 7);   // row within 16-row A tile
    const int achk = (l >> 4);                        // k chunk (0/1) within tile
    const int axor = (arow >> 1) & 3;
    const int brow = ((l >> 4) << 3) + (l & 7);       // row within 16-row B pair
    const int bchk = (l >> 3) & 1;
    const int bxor = (brow >> 1) & 3;

    for (int i = 0; i < NC; i++) {
        CP_WAIT2();
        __syncthreads();
        if (i + 3 < NC)
            tg_load_stage(sbase + ((i + 3) & 3) * 32768, Ahb, Alb, Bhb, Blb, K, (i + 3) * 32, tid);
        CP_COMMIT();

        const uint32_t sb = sbase + (i & 3) * 32768;
        #pragma unroll
        for (int ks = 0; ks < 2; ks++) {
            uint32_t aH[4][4], aL[4][4], bH[4][2], bL[4][2];
            #pragma unroll
            for (int im = 0; im < 4; im++) {
                int row = warp_m * 64 + im * 16 + arow;
                uint32_t ad = sb + row * 64 + (((ks * 2 + achk) ^ axor) << 4);
                LDSM4(aH[im], ad);
                LDSM4(aL[im], ad + 8192);
            }
            #pragma unroll
            for (int p = 0; p < 2; p++) {
                int row = warp_n * 32 + p * 16 + brow;
                uint32_t bd = sb + 16384 + row * 64 + (((ks * 2 + bchk) ^ bxor) << 4);
                uint32_t r4[4];
                LDSM4(r4, bd);
                bH[p*2][0] = r4[0]; bH[p*2][1] = r4[1]; bH[p*2+1][0] = r4[2]; bH[p*2+1][1] = r4[3];
                LDSM4(r4, bd + 8192);
                bL[p*2][0] = r4[0]; bL[p*2][1] = r4[1]; bL[p*2+1][0] = r4[2]; bL[p*2+1][1] = r4[3];
            }
            #pragma unroll
            for (int im = 0; im < 4; im++)
                #pragma unroll
                for (int in = 0; in < 4; in++) {
                    MMA_BF16(acc[im][in], aH[im], bH[in]);
                    MMA_BF16(acc[im][in], aH[im], bL[in]);
                    MMA_BF16(acc[im][in], aL[im], bH[in]);
                }
        }
    }

    // epilogue
    #pragma unroll
    for (int im = 0; im < 4; im++) {
        const int r0 = blockIdx.y * 128 + warp_m * 64 + im * 16 + (l >> 2);
        #pragma unroll
        for (int in = 0; in < 4; in++) {
            const int c0 = blockIdx.x * 128 + warp_n * 32 + in * 8 + (l & 3) * 2;
            float b0 = bias[c0], b1 = bias[c0 + 1];
            float v00 = acc[im][in][0] + b0, v01 = acc[im][in][1] + b1;
            float v10 = acc[im][in][2] + b0, v11 = acc[im][in][3] + b1;
            if (ACT == 1) {
                v00 = fmaxf(v00, 0.f); v01 = fmaxf(v01, 0.f);
                v10 = fmaxf(v10, 0.f); v11 = fmaxf(v11, 0.f);
            }
            if (ACT == 2) {
                v00 = tanhf(v00); v01 = tanhf(v01);
                v10 = tanhf(v10); v11 = tanhf(v11);
            }
            if (OSPLIT == 0) {
                *(float2*)(C + (size_t)r0 * N + c0)       = make_float2(v00, v01);
                *(float2*)(C + (size_t)(r0 + 8) * N + c0) = make_float2(v10, v11);
            } else {
                union { __nv_bfloat16 b[2]; uint32_t u; } h0, l0, h1, l1;
                split_bf16(v00, h0.b[0], l0.b[0]); split_bf16(v01, h0.b[1], l0.b[1]);
                split_bf16(v10, h1.b[0], l1.b[0]); split_bf16(v11, h1.b[1], l1.b[1]);
                *(uint32_t*)(Chi + (size_t)r0 * N + c0)       = h0.u;
                *(uint32_t*)(Clo + (size_t)r0 * N + c0)       = l0.u;
                *(uint32_t*)(Chi + (size_t)(r0 + 8) * N + c0) = h1.u;
                *(uint32_t*)(Clo + (size_t)(r0 + 8) * N + c0) = l1.u;
            }
        }
    }
}

// -------------------- fused attention (fp32), epilogue writes bf16 split ----
__global__ void __launch_bounds__(256) attn_kernel(
    const float* __restrict__ qkv, __nv_bfloat16* __restrict__ Oh, __nv_bfloat16* __restrict__ Ol)
{
    extern __shared__ float sm[];
    float* Vs = sm;                 // [256][64]
    float* Qt = sm + 256 * 64;      // [64][64]
    float* Kt = Qt + 64 * 64;       // [64][256]
    float* St = sm + 256 * 64;      // [256][68]

    const int tid   = threadIdx.x;
    const int qtile = blockIdx.x;
    const int bh    = blockIdx.y;
    const int b = bh / NH, h = bh % NH;
    const float* base = qkv + (size_t)b * SEQ * E3 + h * HDIM;

    #pragma unroll
    for (int i = 0; i < 16; i++) {
        int idx = tid + i * 256;
        int row = idx >> 4;
        int c4  = (idx & 15) << 2;
        float4 kv = *(const float4*)(base + (size_t)row * E3 + EDIM     + c4);
        float4 vv = *(const float4*)(base + (size_t)row * E3 + 2 * EDIM + c4);
        *(float4*)&Vs[row * 64 + c4] = vv;
        Kt[(c4 + 0) * 256 + row] = kv.x; Kt[(c4 + 1) * 256 + row] = kv.y;
        Kt[(c4 + 2) * 256 + row] = kv.z; Kt[(c4 + 3) * 256 + row] = kv.w;
    }
    #pragma unroll
    for (int i = 0; i < 4; i++) {
        int idx = tid + i * 256;
        int row = idx >> 4;
        int c4  = (idx & 15) << 2;
        float4 qv = *(const float4*)(base + (size_t)(qtile * 64 + row) * E3 + c4);
        Qt[(c4 + 0) * 64 + row] = qv.x; Qt[(c4 + 1) * 64 + row] = qv.y;
        Qt[(c4 + 2) * 64 + row] = qv.z; Qt[(c4 + 3) * 64 + row] = qv.w;
    }
    __syncthreads();

    {
        const int tx = tid & 31, ty = tid >> 5;
        float acc[8][8];
        #pragma unroll
        for (int i = 0; i < 8; i++)
            #pragma unroll
            for (int j = 0; j < 8; j++) acc[i][j] = 0.f;
        for (int k = 0; k < 64; k++) {
            float ar[8], br[8];
            *(float4*)&ar[0] = *(const float4*)&Qt[k * 64  + ty * 8];
            *(float4*)&ar[4] = *(const float4*)&Qt[k * 64  + ty * 8 + 4];
            *(float4*)&br[0] = *(const float4*)&Kt[k * 256 + tx * 8];
            *(float4*)&br[4] = *(const float4*)&Kt[k * 256 + tx * 8 + 4];
            #pragma unroll
            for (int i = 0; i < 8; i++)
                #pragma unroll
                for (int j = 0; j < 8; j++)
                    acc[i][j] += ar[i] * br[j];
        }
        __syncthreads();
        #pragma unroll
        for (int j = 0; j < 8; j++)
            #pragma unroll
            for (int i = 0; i < 8; i++)
                St[(tx * 8 + j) * 68 + ty * 8 + i] = acc[i][j] * 0.125f;
    }
    __syncthreads();

    {
        const int q = tid >> 2, part = tid & 3;
        float mx = -1e30f;
        for (int j = 0; j < 64; j++) mx = fmaxf(mx, St[(part * 64 + j) * 68 + q]);
        mx = fmaxf(mx, __shfl_xor_sync(0xffffffffu, mx, 1));
        mx = fmaxf(mx, __shfl_xor_sync(0xffffffffu, mx, 2));
        float ssum = 0.f;
        for (int j = 0; j < 64; j++) ssum += expf(St[(part * 64 + j) * 68 + q] - mx);
        ssum += __shfl_xor_sync(0xffffffffu, ssum, 1);
        ssum += __shfl_xor_sync(0xffffffffu, ssum, 2);
        float inv = 1.0f / ssum;
        for (int j = 0; j < 64; j++) {
            int r = part * 64 + j;
            St[r * 68 + q] = expf(St[r * 68 + q] - mx) * inv;
        }
    }
    __syncthreads();

    {
        const int tx = tid & 15, ty = tid >> 4;
        float acc[4][4];
        #pragma unroll
        for (int i = 0; i < 4; i++)
            #pragma unroll
            for (int j = 0; j < 4; j++) acc[i][j] = 0.f;
        for (int k = 0; k < 256; k++) {
            float4 a  = *(const float4*)&St[k * 68 + ty * 4];
            float4 bv = *(const float4*)&Vs[k * 64 + tx * 4];
            float ar[4] = {a.x, a.y, a.z, a.w};
            float br[4] = {bv.x, bv.y, bv.z, bv.w};
            #pragma unroll
            for (int i = 0; i < 4; i++)
                #pragma unroll
                for (int j = 0; j < 4; j++)
                    acc[i][j] += ar[i] * br[j];
        }
        #pragma unroll
        for (int i = 0; i < 4; i++) {
            int t = b * SEQ + qtile * 64 + ty * 4 + i;
            size_t o = (size_t)t * EDIM + h * HDIM + tx * 4;
            union { __nv_bfloat16 b4[4]; uint2 u; } ph, pl;
            #pragma unroll
            for (int j = 0; j < 4; j++) split_bf16(acc[i][j], ph.b4[j], pl.b4[j]);
            *(uint2*)(Oh + o) = ph.u;
            *(uint2*)(Ol + o) = pl.u;
        }
    }
}

// -------------------- cosine --------------------
__global__ void __launch_bounds__(256) cos_kernel(
    const float* __restrict__ tok, const float* __restrict__ out, float* __restrict__ cosb)
{
    const int t = blockIdx.x * 8 + (threadIdx.x >> 5);
    const int l = threadIdx.x & 31;
    const float* a = tok + (size_t)t * EDIM;
    const float* b = out + (size_t)t * EDIM;
    float dot = 0.f, na = 0.f, nb = 0.f;
    for (int i = l; i < EDIM; i += 32) {
        float x = a[i], y = b[i];
        dot += x * y; na += x * x; nb += y * y;
    }
    #pragma unroll
    for (int o = 16; o > 0; o >>= 1) {
        dot += __shfl_xor_sync(0xffffffffu, dot, o);
        na  += __shfl_xor_sync(0xffffffffu, na,  o);
        nb  += __shfl_xor_sync(0xffffffffu, nb,  o);
    }
    if (l == 0)
        cosb[t] = dot / fmaxf(sqrtf(na) * sqrtf(nb), 1e-8f);
}

// -------------------- masked softmax + gumbel top-k --------------------
__global__ void __launch_bounds__(256) topk_kernel(
    const float* __restrict__ cosb, const float* __restrict__ gh, const float* __restrict__ gt,
    const int* __restrict__ typ, float* __restrict__ out)
{
    __shared__ float red[8];
    __shared__ float glh[256], glt[256];
    const int b = blockIdx.x, s = threadIdx.x;
    const int idx = b * SEQ + s;
    const int t = typ[idx];
    const float c = cosb[idx];
    const bool vh = (t == 1), vt = (t == 2);
    float eh = vh ? expf(c) : 0.f;
    float et = vt ? expf(c) : 0.f;
    float Zh = block_sum256(eh, red);
    float Zt = block_sum256(et, red);
    glh[s] = vh ? (logf(eh / Zh) + gh[idx]) : -1e30f;
    glt[s] = vt ? (logf(1.0f - et / Zt) + gt[idx]) : -1e30f;
    __syncthreads();
    int ch = 0, ct = 0;
    const float mh = glh[s], mt = glt[s];
    for (int j = 0; j < 256; j++) {
        float a = glh[j], d = glt[j];
        ch += (a > mh) || (a == mh && j < s);
        ct += (d > mt) || (d == mt && j < s);
    }
    float r = 0.f;
    if (vh && ch < 64) r += 1.0f;
    if (vt && ct < 63) r += 1.0f;
    out[idx] = r;
}

// -------------------- host orchestration --------------------
extern "C" void kernel_launch(void* const* d_in, const int* in_sizes, int n_in,
                              void* d_out, int out_size)
{
    const float* tok  = (const float*)d_in[0];
    const int*   pos  = (const int*)  d_in[2];
    const int*   typ  = (const int*)  d_in[3];
    const float* gh   = (const float*)d_in[4];
    const float* gt   = (const float*)d_in[5];
    const float* pe   = (const float*)d_in[6];
    const float* temb = (const float*)d_in[7];
    const float* lnw  = (const float*)d_in[8];
    const float* lnb  = (const float*)d_in[9];
    const float* dw   = (const float*)d_in[10];
    const float* db   = (const float*)d_in[11];
    const float* qkvw = (const float*)d_in[12];
    const float* qkvb = (const float*)d_in[13];
    const float* ow   = (const float*)d_in[14];
    const float* obv  = (const float*)d_in[15];
    const float* ln1w = (const float*)d_in[16];
    const float* ln1b = (const float*)d_in[17];
    const float* l1w  = (const float*)d_in[18];
    const float* l1b  = (const float*)d_in[19];
    const float* l2w  = (const float*)d_in[20];
    const float* l2b  = (const float*)d_in[21];
    const float* ln2w = (const float*)d_in[22];
    const float* ln2b = (const float*)d_in[23];

    float *X, *Y, *QKV, *O, *C;
    __nv_bfloat16 *Ah, *Al, *Fh, *Fl;
    __nv_bfloat16 *Wqh, *Wql, *Woh, *Wol, *W1h, *W1l, *W2h, *W2l, *Wdh, *Wdl;
    cudaGetSymbolAddress((void**)&X,   g_X);
    cudaGetSymbolAddress((void**)&Y,   g_Yb);
    cudaGetSymbolAddress((void**)&QKV, g_QKV);
    cudaGetSymbolAddress((void**)&O,   g_O);
    cudaGetSymbolAddress((void**)&C,   g_C);
    cudaGetSymbolAddress((void**)&Ah,  g_Ah);
    cudaGetSymbolAddress((void**)&Al,  g_Al);
    cudaGetSymbolAddress((void**)&Fh,  g_Fh);
    cudaGetSymbolAddress((void**)&Fl,  g_Fl);
    cudaGetSymbolAddress((void**)&Wqh, g_Wqkv_h); cudaGetSymbolAddress((void**)&Wql, g_Wqkv_l);
    cudaGetSymbolAddress((void**)&Woh, g_Wout_h); cudaGetSymbolAddress((void**)&Wol, g_Wout_l);
    cudaGetSymbolAddress((void**)&W1h, g_W1_h);   cudaGetSymbolAddress((void**)&W1l, g_W1_l);
    cudaGetSymbolAddress((void**)&W2h, g_W2_h);   cudaGetSymbolAddress((void**)&W2l, g_W2_l);
    cudaGetSymbolAddress((void**)&Wdh, g_Wd_h);   cudaGetSymbolAddress((void**)&Wdl, g_Wd_l);

    const int ATTN_SMEM = (256 * 64 + 64 * 64 + 64 * 256) * 4;
    cudaFuncSetAttribute(attn_kernel, cudaFuncAttributeMaxDynamicSharedMemorySize, ATTN_SMEM);
    cudaFuncSetAttribute(tgemm_kernel<0,0>, cudaFuncAttributeMaxDynamicSharedMemorySize, TG_SMEM);
    cudaFuncSetAttribute(tgemm_kernel<1,1>, cudaFuncAttributeMaxDynamicSharedMemorySize, TG_SMEM);
    cudaFuncSetAttribute(tgemm_kernel<2,0>, cudaFuncAttributeMaxDynamicSharedMemorySize, TG_SMEM);

    // weight conversions
    cvt_kernel<<<1024, 256>>>(qkvw, Wqh, Wql, 2 * E3 * EDIM / 4);
    cvt_kernel<<<1024, 256>>>(ow,   Woh, Wol, 2 * EDIM * EDIM / 4);
    cvt_kernel<<<1024, 256>>>(l1w,  W1h, W1l, 2 * FFDIM * EDIM / 4);
    cvt_kernel<<<1024, 256>>>(l2w,  W2h, W2l, 2 * EDIM * FFDIM / 4);
    cvt_kernel<<<1024, 256>>>(dw,   Wdh, Wdl, EDIM * EDIM / 4);

    embed_ln_kernel<<<NTOK, 256>>>(tok, pos, typ, pe, temb, lnw, lnb, X, Ah, Al);

    for (int l = 0; l < 2; l++) {
        tgemm_kernel<0,0><<<dim3(E3 / 128, NTOK / 128), 256, TG_SMEM>>>(
            Ah, Al, Wqh + (size_t)l * E3 * EDIM, Wql + (size_t)l * E3 * EDIM,
            qkvb + (size_t)l * E3, QKV, nullptr, nullptr, NTOK, E3, EDIM);
        attn_kernel<<<dim3(4, NB * NH), 256, ATTN_SMEM>>>(QKV, Ah, Al);
        tgemm_kernel<0,0><<<dim3(EDIM / 128, NTOK / 128), 256, TG_SMEM>>>(
            Ah, Al, Woh + (size_t)l * EDIM * EDIM, Wol + (size_t)l * EDIM * EDIM,
            obv + (size_t)l * EDIM, Y, nullptr, nullptr, NTOK, EDIM, EDIM);
        addln_kernel<true><<<NTOK, 256>>>(X, Y, ln1w + (size_t)l * EDIM, ln1b + (size_t)l * EDIM, X, Ah, Al);
        tgemm_kernel<1,1><<<dim3(FFDIM / 128, NTOK / 128), 256, TG_SMEM>>>(
            Ah, Al, W1h + (size_t)l * FFDIM * EDIM, W1l + (size_t)l * FFDIM * EDIM,
            l1b + (size_t)l * FFDIM, nullptr, Fh, Fl, NTOK, FFDIM, EDIM);
        tgemm_kernel<0,0><<<dim3(EDIM / 128, NTOK / 128), 256, TG_SMEM>>>(
            Fh, Fl, W2h + (size_t)l * EDIM * FFDIM, W2l + (size_t)l * EDIM * FFDIM,
            l2b + (size_t)l * EDIM, Y, nullptr, nullptr, NTOK, EDIM, FFDIM);
        addln_kernel<true><<<NTOK, 256>>>(X, Y, ln2w + (size_t)l * EDIM, ln2b + (size_t)l * EDIM, X, Ah, Al);
    }

    addln_kernel<false><<<NTOK, 256>>>(X, nullptr, lnw, lnb, Y, Ah, Al);
    tgemm_kernel<2,0><<<dim3(EDIM / 128, NTOK / 128), 256, TG_SMEM>>>(
        Ah, Al, Wdh, Wdl, db, O, nullptr, nullptr, NTOK, EDIM, EDIM);
    cos_kernel<<<NTOK / 8, 256>>>(tok, O, C);
    topk_kernel<<<NB, 256>>>(C, gh, gt, typ, (float*)d_out);
}

// round 5
// speedup vs baseline: 2.5376x; 1.1587x over previous
#include <cuda_runtime.h>
#include <cuda_bf16.h>
#include <math.h>
#include <stdint.h>

// Problem constants
#define NTOK   8192
#define EDIM   768
#define SEQ    256
#define NB     32
#define NH     12
#define HDIM   64
#define FFDIM  2048
#define E3     2304

// -------------------- scratch --------------------
__device__ float g_X  [NTOK * EDIM];
__device__ float g_Yb [NTOK * EDIM];
__device__ float g_O  [NTOK * EDIM];
__device__ float g_C  [NTOK];

__device__ __nv_bfloat16 g_Ah[NTOK * EDIM],  g_Al[NTOK * EDIM];
__device__ __nv_bfloat16 g_Fh[NTOK * FFDIM], g_Fl[NTOK * FFDIM];
__device__ __nv_bfloat16 g_QKVh[NTOK * E3],  g_QKVl[NTOK * E3];
__device__ __nv_bfloat16 g_Wqkv_h[2 * E3 * EDIM],   g_Wqkv_l[2 * E3 * EDIM];
__device__ __nv_bfloat16 g_Wout_h[2 * EDIM * EDIM], g_Wout_l[2 * EDIM * EDIM];
__device__ __nv_bfloat16 g_W1_h[2 * FFDIM * EDIM],  g_W1_l[2 * FFDIM * EDIM];
__device__ __nv_bfloat16 g_W2_h[2 * EDIM * FFDIM],  g_W2_l[2 * EDIM * FFDIM];
__device__ __nv_bfloat16 g_Wd_h[EDIM * EDIM],       g_Wd_l[EDIM * EDIM];

// -------------------- helpers --------------------
__device__ __forceinline__ uint32_t smem_u32(const void* p) {
    uint32_t a;
    asm("{ .reg .u64 t; cvta.to.shared.u64 t, %1; cvt.u32.u64 %0, t; }" : "=r"(a) : "l"(p));
    return a;
}
__device__ __forceinline__ void split_bf16(float v, __nv_bfloat16& h, __nv_bfloat16& l) {
    h = __float2bfloat16(v);
    l = __float2bfloat16(v - __bfloat162float(h));
}

#define CP_ASYNC16(saddr, gptr) \
    asm volatile("cp.async.cg.shared.global [%0], [%1], 16;" :: "r"(saddr), "l"(gptr))
#define CP_COMMIT() asm volatile("cp.async.commit_group;" ::: "memory")
#define CP_WAIT2()  asm volatile("cp.async.wait_group 2;" ::: "memory")
#define CP_WAIT0()  asm volatile("cp.async.wait_group 0;" ::: "memory")

#define LDSM4(r, addr) \
    asm volatile("ldmatrix.sync.aligned.m8n8.x4.shared.b16 {%0,%1,%2,%3}, [%4];" \
        : "=r"((r)[0]), "=r"((r)[1]), "=r"((r)[2]), "=r"((r)[3]) : "r"(addr))
#define LDSM4T(r, addr) \
    asm volatile("ldmatrix.sync.aligned.m8n8.x4.trans.shared.b16 {%0,%1,%2,%3}, [%4];" \
        : "=r"((r)[0]), "=r"((r)[1]), "=r"((r)[2]), "=r"((r)[3]) : "r"(addr))

#define MMA_BF16(c, a, b) \
    asm volatile("mma.sync.aligned.m16n8k16.row.col.f32.bf16.bf16.f32 " \
        "{%0,%1,%2,%3}, {%4,%5,%6,%7}, {%8,%9}, {%0,%1,%2,%3};" \
        : "+f"((c)[0]), "+f"((c)[1]), "+f"((c)[2]), "+f"((c)[3]) \
        : "r"((a)[0]), "r"((a)[1]), "r"((a)[2]), "r"((a)[3]), "r"((b)[0]), "r"((b)[1]))

// -------------------- block reduction (256 threads) --------------------
__device__ __forceinline__ float block_sum256(float v, volatile float* red) {
    #pragma unroll
    for (int o = 16; o > 0; o >>= 1) v += __shfl_xor_sync(0xffffffffu, v, o);
    const int w = threadIdx.x >> 5;
    __syncthreads();
    if ((threadIdx.x & 31) == 0) red[w] = v;
    __syncthreads();
    return red[0] + red[1] + red[2] + red[3] + red[4] + red[5] + red[6] + red[7];
}

// -------------------- fp32 -> (hi,lo) bf16 converter --------------------
__global__ void __launch_bounds__(256) cvt_kernel(
    const float* __restrict__ s, __nv_bfloat16* __restrict__ hi,
    __nv_bfloat16* __restrict__ lo, int n4)
{
    int i = blockIdx.x * 256 + threadIdx.x;
    const int stride = gridDim.x * 256;
    for (; i < n4; i += stride) {
        float4 v = ((const float4*)s)[i];
        union { __nv_bfloat16 b[4]; uint2 u; } ph, pl;
        split_bf16(v.x, ph.b[0], pl.b[0]);
        split_bf16(v.y, ph.b[1], pl.b[1]);
        split_bf16(v.z, ph.b[2], pl.b[2]);
        split_bf16(v.w, ph.b[3], pl.b[3]);
        ((uint2*)hi)[i] = ph.u;
        ((uint2*)lo)[i] = pl.u;
    }
}

// -------------------- embed + LN (fp32 X + hi/lo split) --------------------
__global__ void __launch_bounds__(256) embed_ln_kernel(
    const float* __restrict__ tok, const int* __restrict__ pos, const int* __restrict__ typ,
    const float* __restrict__ pe, const float* __restrict__ temb,
    const float* __restrict__ w, const float* __restrict__ bb, float* __restrict__ X,
    __nv_bfloat16* __restrict__ Xh, __nv_bfloat16* __restrict__ Xl)
{
    __shared__ float red[8];
    const int t = blockIdx.x, tid = threadIdx.x;
    const float* tr = tok  + (size_t)t * EDIM;
    const float* pr = pe   + (size_t)pos[t] * EDIM;
    const float* yr = temb + (size_t)typ[t] * EDIM;
    float v[3];
    #pragma unroll
    for (int i = 0; i < 3; i++) { int c = tid + i * 256; v[i] = tr[c] + pr[c] + yr[c]; }
    float m = block_sum256(v[0] + v[1] + v[2], red) * (1.0f / 768.0f);
    float q = 0.f;
    #pragma unroll
    for (int i = 0; i < 3; i++) { float d = v[i] - m; q += d * d; }
    q = block_sum256(q, red);
    float inv = rsqrtf(q * (1.0f / 768.0f) + 1e-5f);
    #pragma unroll
    for (int i = 0; i < 3; i++) {
        int c = tid + i * 256;
        float o = (v[i] - m) * inv * w[c] + bb[c];
        X[(size_t)t * EDIM + c] = o;
        __nv_bfloat16 h, l; split_bf16(o, h, l);
        Xh[(size_t)t * EDIM + c] = h;
        Xl[(size_t)t * EDIM + c] = l;
    }
}

// -------------------- residual + LN (fp32 X + hi/lo split) --------------------
template<bool ADD>
__global__ void __launch_bounds__(256) addln_kernel(
    const float* __restrict__ Xin, const float* __restrict__ Y,
    const float* __restrict__ w, const float* __restrict__ bb, float* __restrict__ Xout,
    __nv_bfloat16* __restrict__ Xh, __nv_bfloat16* __restrict__ Xl)
{
    __shared__ float red[8];
    const int t = blockIdx.x, tid = threadIdx.x;
    float v[3];
    #pragma unroll
    for (int i = 0; i < 3; i++) {
        int c = tid + i * 256;
        float x = Xin[(size_t)t * EDIM + c];
        if (ADD) x += Y[(size_t)t * EDIM + c];
        v[i] = x;
    }
    float m = block_sum256(v[0] + v[1] + v[2], red) * (1.0f / 768.0f);
    float q = 0.f;
    #pragma unroll
    for (int i = 0; i < 3; i++) { float d = v[i] - m; q += d * d; }
    q = block_sum256(q, red);
    float inv = rsqrtf(q * (1.0f / 768.0f) + 1e-5f);
    #pragma unroll
    for (int i = 0; i < 3; i++) {
        int c = tid + i * 256;
        float o = (v[i] - m) * inv * w[c] + bb[c];
        Xout[(size_t)t * EDIM + c] = o;
        __nv_bfloat16 h, l; split_bf16(o, h, l);
        Xh[(size_t)t * EDIM + c] = h;
        Xl[(size_t)t * EDIM + c] = l;
    }
}

// -------------------- mma.sync split-bf16 GEMM --------------------
#define TG_SMEM (4 * 32768)

__device__ __forceinline__ void tg_load_stage(
    uint32_t sb, const __nv_bfloat16* __restrict__ Ahb, const __nv_bfloat16* __restrict__ Alb,
    const __nv_bfloat16* __restrict__ Bhb, const __nv_bfloat16* __restrict__ Blb,
    int K, int kc, int tid)
{
    #pragma unroll
    for (int t = 0; t < 2; t++) {
        int idx = tid + t * 256;          // 0..511
        int row = idx >> 2;               // 0..127
        int ch  = idx & 3;
        uint32_t soff = (uint32_t)(row * 64 + ((ch ^ ((row >> 1) & 3)) << 4));
        size_t goff = (size_t)row * K + kc + ch * 8;
        CP_ASYNC16(sb +         soff, Ahb + goff);
        CP_ASYNC16(sb +  8192 + soff, Alb + goff);
        CP_ASYNC16(sb + 16384 + soff, Bhb + goff);
        CP_ASYNC16(sb + 24576 + soff, Blb + goff);
    }
}

template<int ACT, int OSPLIT>   // ACT: 0=none 1=relu 2=tanh; OSPLIT: 0 fp32 C, 1 bf16 hi/lo
__global__ void __launch_bounds__(256) tgemm_kernel(
    const __nv_bfloat16* __restrict__ Ah, const __nv_bfloat16* __restrict__ Al,
    const __nv_bfloat16* __restrict__ Bh, const __nv_bfloat16* __restrict__ Bl,
    const float* __restrict__ bias, float* __restrict__ C,
    __nv_bfloat16* __restrict__ Chi, __nv_bfloat16* __restrict__ Clo,
    int M, int N, int K)
{
    extern __shared__ __align__(128) unsigned char dsm[];
    const uint32_t sbase = smem_u32(dsm);
    const int tid = threadIdx.x;
    const int w = tid >> 5, l = tid & 31;
    const int warp_m = w & 1;
    const int warp_n = w >> 1;
    const int NC = K >> 5;

    const __nv_bfloat16* Ahb = Ah + (size_t)blockIdx.y * 128 * K;
    const __nv_bfloat16* Alb = Al + (size_t)blockIdx.y * 128 * K;
    const __nv_bfloat16* Bhb = Bh + (size_t)blockIdx.x * 128 * K;
    const __nv_bfloat16* Blb = Bl + (size_t)blockIdx.x * 128 * K;

    #pragma unroll
    for (int s = 0; s < 3; s++) {
        tg_load_stage(sbase + s * 32768, Ahb, Alb, Bhb, Blb, K, s * 32, tid);
        CP_COMMIT();
    }

    float acc[4][4][4];
    #pragma unroll
    for (int im = 0; im < 4; im++)
        #pragma unroll
        for (int in = 0; in < 4; in++)
            #pragma unroll
            for (int r = 0; r < 4; r++) acc[im][in][r] = 0.f;

    const int arow = ((l >> 3) & 1) * 8 + (l & 7);
    const int achk = (l >> 4);
    const int axor = (arow >> 1) & 3;
    const int brow = ((l >> 4) << 3) + (l & 7);
    const int bchk = (l >> 3) & 1;
    const int bxor = (brow >> 1) & 3;

    for (int i = 0; i < NC; i++) {
        CP_WAIT2();
        __syncthreads();
        if (i + 3 < NC)
            tg_load_stage(sbase + ((i + 3) & 3) * 32768, Ahb, Alb, Bhb, Blb, K, (i + 3) * 32, tid);
        CP_COMMIT();

        const uint32_t sb = sbase + (i & 3) * 32768;
        #pragma unroll
        for (int ks = 0; ks < 2; ks++) {
            uint32_t aH[4][4], aL[4][4], bH[4][2], bL[4][2];
            #pragma unroll
            for (int im = 0; im < 4; im++) {
                int row = warp_m * 64 + im * 16 + arow;
                uint32_t ad = sb + row * 64 + (((ks * 2 + achk) ^ axor) << 4);
                LDSM4(aH[im], ad);
                LDSM4(aL[im], ad + 8192);
            }
            #pragma unroll
            for (int p = 0; p < 2; p++) {
                int row = warp_n * 32 + p * 16 + brow;
                uint32_t bd = sb + 16384 + row * 64 + (((ks * 2 + bchk) ^ bxor) << 4);
                uint32_t r4[4];
                LDSM4(r4, bd);
                bH[p*2][0] = r4[0]; bH[p*2][1] = r4[1]; bH[p*2+1][0] = r4[2]; bH[p*2+1][1] = r4[3];
                LDSM4(r4, bd + 8192);
                bL[p*2][0] = r4[0]; bL[p*2][1] = r4[1]; bL[p*2+1][0] = r4[2]; bL[p*2+1][1] = r4[3];
            }
            #pragma unroll
            for (int im = 0; im < 4; im++)
                #pragma unroll
                for (int in = 0; in < 4; in++) {
                    MMA_BF16(acc[im][in], aH[im], bH[in]);
                    MMA_BF16(acc[im][in], aH[im], bL[in]);
                    MMA_BF16(acc[im][in], aL[im], bH[in]);
                }
        }
    }

    #pragma unroll
    for (int im = 0; im < 4; im++) {
        const int r0 = blockIdx.y * 128 + warp_m * 64 + im * 16 + (l >> 2);
        #pragma unroll
        for (int in = 0; in < 4; in++) {
            const int c0 = blockIdx.x * 128 + warp_n * 32 + in * 8 + (l & 3) * 2;
            float b0 = bias[c0], b1 = bias[c0 + 1];
            float v00 = acc[im][in][0] + b0, v01 = acc[im][in][1] + b1;
            float v10 = acc[im][in][2] + b0, v11 = acc[im][in][3] + b1;
            if (ACT == 1) {
                v00 = fmaxf(v00, 0.f); v01 = fmaxf(v01, 0.f);
                v10 = fmaxf(v10, 0.f); v11 = fmaxf(v11, 0.f);
            }
            if (ACT == 2) {
                v00 = tanhf(v00); v01 = tanhf(v01);
                v10 = tanhf(v10); v11 = tanhf(v11);
            }
            if (OSPLIT == 0) {
                *(float2*)(C + (size_t)r0 * N + c0)       = make_float2(v00, v01);
                *(float2*)(C + (size_t)(r0 + 8) * N + c0) = make_float2(v10, v11);
            } else {
                union { __nv_bfloat16 b[2]; uint32_t u; } h0, l0, h1, l1;
                split_bf16(v00, h0.b[0], l0.b[0]); split_bf16(v01, h0.b[1], l0.b[1]);
                split_bf16(v10, h1.b[0], l1.b[0]); split_bf16(v11, h1.b[1], l1.b[1]);
                *(uint32_t*)(Chi + (size_t)r0 * N + c0)       = h0.u;
                *(uint32_t*)(Clo + (size_t)r0 * N + c0)       = l0.u;
                *(uint32_t*)(Chi + (size_t)(r0 + 8) * N + c0) = h1.u;
                *(uint32_t*)(Clo + (size_t)(r0 + 8) * N + c0) = l1.u;
            }
        }
    }
}

// -------------------- tensor-core attention --------------------
// CTA = (qtile of 128 rows, b*h). smem 224KB:
//   [0,64K)    S0: S[:,0:128] fp32 (swizzled) -> later Ph (128x256 bf16)
//   [64K,128K) S1: S[:,128:256] fp32          -> later Pl
//   [128K,160K) Qh,Ql (16K each)
//   [160K,224K) Kh,Kl (32K each) -> reused as Vh,Vl
#define ATTN_SMEM2 (224 * 1024)

__global__ void __launch_bounds__(256) attn_mma_kernel(
    const __nv_bfloat16* __restrict__ QKVh, const __nv_bfloat16* __restrict__ QKVl,
    __nv_bfloat16* __restrict__ Oh, __nv_bfloat16* __restrict__ Ol)
{
    extern __shared__ __align__(128) unsigned char asm_[];
    const uint32_t S0 = smem_u32(asm_);
    const uint32_t S1 = S0 + 65536;
    const uint32_t QH = S0 + 131072;     // QL = QH + 16384
    const uint32_t KH = S0 + 163840;     // KL = KH + 32768 (V reuses)

    const int tid = threadIdx.x;
    const int w = tid >> 5, lane = tid & 31;
    const int qt = blockIdx.x;            // 0..1
    const int bh = blockIdx.y;            // 0..383
    const int b = bh / NH, h = bh % NH;
    const size_t tok0 = (size_t)b * SEQ;

    // ---- load Q (128 rows) + K (256 rows), hi/lo ----
    #pragma unroll
    for (int i = 0; i < 4; i++) {
        int idx = tid + i * 256; int r = idx >> 3, ch = idx & 7;
        uint32_t so = r * 128 + ((ch ^ (r & 7)) << 4);
        size_t go = (tok0 + qt * 128 + r) * E3 + h * HDIM + ch * 8;
        CP_ASYNC16(QH + so, QKVh + go);
        CP_ASYNC16(QH + 16384 + so, QKVl + go);
    }
    #pragma unroll
    for (int i = 0; i < 8; i++) {
        int idx = tid + i * 256; int r = idx >> 3, ch = idx & 7;
        uint32_t so = r * 128 + ((ch ^ (r & 7)) << 4);
        size_t go = (tok0 + r) * E3 + EDIM + h * HDIM + ch * 8;
        CP_ASYNC16(KH + so, QKVh + go);
        CP_ASYNC16(KH + 32768 + so, QKVl + go);
    }
    CP_COMMIT();
    CP_WAIT0();
    __syncthreads();

    // ---- GEMM1: S = Q @ K^T / 8 (two 128-col halves) ----
    const int warp_m = w & 1, warp_n = w >> 1;
    const int a_r = lane & 15;
    const int a_c = lane >> 4;
    const int b_r = ((lane >> 4) << 3) + (lane & 7);
    const int b_c = (lane >> 3) & 1;

    #pragma unroll
    for (int half = 0; half < 2; half++) {
        float acc[4][4][4];
        #pragma unroll
        for (int im = 0; im < 4; im++)
            #pragma unroll
            for (int in = 0; in < 4; in++)
                #pragma unroll
                for (int r = 0; r < 4; r++) acc[im][in][r] = 0.f;

        #pragma unroll
        for (int ks = 0; ks < 4; ks++) {
            uint32_t aH[4][4], aL[4][4], bH[4][2], bL[4][2];
            #pragma unroll
            for (int im = 0; im < 4; im++) {
                int r = warp_m * 64 + im * 16 + a_r;
                int cc = ks * 2 + a_c;
                uint32_t ad = QH + r * 128 + ((cc ^ (r & 7)) << 4);
                LDSM4(aH[im], ad);
                LDSM4(aL[im], ad + 16384);
            }
            #pragma unroll
            for (int p = 0; p < 2; p++) {
                int r = half * 128 + warp_n * 32 + p * 16 + b_r;
                int cc = ks * 2 + b_c;
                uint32_t bd = KH + r * 128 + ((cc ^ (r & 7)) << 4);
                uint32_t t4[4];
                LDSM4(t4, bd);
                bH[p*2][0] = t4[0]; bH[p*2][1] = t4[1]; bH[p*2+1][0] = t4[2]; bH[p*2+1][1] = t4[3];
                LDSM4(t4, bd + 32768);
                bL[p*2][0] = t4[0]; bL[p*2][1] = t4[1]; bL[p*2+1][0] = t4[2]; bL[p*2+1][1] = t4[3];
            }
            #pragma unroll
            for (int im = 0; im < 4; im++)
                #pragma unroll
                for (int in = 0; in < 4; in++) {
                    MMA_BF16(acc[im][in], aH[im], bH[in]);
                    MMA_BF16(acc[im][in], aH[im], bL[in]);
                    MMA_BF16(acc[im][in], aL[im], bH[in]);
                }
        }

        // write S half (fp32, 16B-chunk swizzle within 512B rows), scaled 1/8
        const uint32_t Sb = (half == 0) ? S0 : S1;
        #pragma unroll
        for (int im = 0; im < 4; im++) {
            int r0 = warp_m * 64 + im * 16 + (lane >> 2);
            int r1 = r0 + 8;
            #pragma unroll
            for (int in = 0; in < 4; in++) {
                int c = warp_n * 32 + in * 8 + (lane & 3) * 2;
                uint32_t a0 = Sb + r0 * 512 + (((c >> 2) ^ (r0 & 7)) << 4) + (c & 3) * 4;
                uint32_t a1 = Sb + r1 * 512 + (((c >> 2) ^ (r1 & 7)) << 4) + (c & 3) * 4;
                asm volatile("st.shared.v2.f32 [%0], {%1,%2};"
                    :: "r"(a0), "f"(acc[im][in][0] * 0.125f), "f"(acc[im][in][1] * 0.125f) : "memory");
                asm volatile("st.shared.v2.f32 [%0], {%1,%2};"
                    :: "r"(a1), "f"(acc[im][in][2] * 0.125f), "f"(acc[im][in][3] * 0.125f) : "memory");
            }
        }
    }
    __syncthreads();   // all K reads + S writes done

    // ---- load V into old K region ----
    #pragma unroll
    for (int i = 0; i < 8; i++) {
        int idx = tid + i * 256; int r = idx >> 3, ch = idx & 7;
        uint32_t so = r * 128 + ((ch ^ (r & 7)) << 4);
        size_t go = (tok0 + r) * E3 + 2 * EDIM + h * HDIM + ch * 8;
        CP_ASYNC16(KH + so, QKVh + go);
        CP_ASYNC16(KH + 32768 + so, QKVl + go);
    }
    CP_COMMIT();

    // ---- softmax rows w*16..w*16+15; P -> bf16 hi/lo in place over S0/S1 ----
    for (int rr = 0; rr < 16; rr++) {
        const int r = w * 16 + rr;
        const uint32_t Sb = (lane < 16) ? S0 : S1;
        const int ch2 = 2 * (lane & 15);
        const uint32_t base = Sb + r * 512;
        float v[8];
        asm volatile("ld.shared.v4.f32 {%0,%1,%2,%3}, [%4];"
            : "=f"(v[0]), "=f"(v[1]), "=f"(v[2]), "=f"(v[3])
            : "r"(base + ((ch2 ^ (r & 7)) << 4)));
        asm volatile("ld.shared.v4.f32 {%0,%1,%2,%3}, [%4];"
            : "=f"(v[4]), "=f"(v[5]), "=f"(v[6]), "=f"(v[7])
            : "r"(base + (((ch2 + 1) ^ (r & 7)) << 4)));
        float mx = v[0];
        #pragma unroll
        for (int j = 1; j < 8; j++) mx = fmaxf(mx, v[j]);
        #pragma unroll
        for (int o = 16; o > 0; o >>= 1) mx = fmaxf(mx, __shfl_xor_sync(0xffffffffu, mx, o));
        float s = 0.f;
        #pragma unroll
        for (int j = 0; j < 8; j++) { v[j] = expf(v[j] - mx); s += v[j]; }
        #pragma unroll
        for (int o = 16; o > 0; o >>= 1) s += __shfl_xor_sync(0xffffffffu, s, o);
        const float inv = 1.0f / s;
        union { __nv_bfloat16 b[8]; uint4 u; } ph, pl;
        #pragma unroll
        for (int j = 0; j < 8; j++) {
            float p = v[j] * inv;
            split_bf16(p, ph.b[j], pl.b[j]);
        }
        __syncwarp();
        const uint32_t pc = r * 512 + ((lane ^ (r & 7)) << 4);
        asm volatile("st.shared.v4.b32 [%0], {%1,%2,%3,%4};"
            :: "r"(S0 + pc), "r"(ph.u.x), "r"(ph.u.y), "r"(ph.u.z), "r"(ph.u.w) : "memory");
        asm volatile("st.shared.v4.b32 [%0], {%1,%2,%3,%4};"
            :: "r"(S1 + pc), "r"(pl.u.x), "r"(pl.u.y), "r"(pl.u.z), "r"(pl.u.w) : "memory");
    }
    CP_WAIT0();
    __syncthreads();   // V ready, all P written

    // ---- GEMM2: O[128,64] = P[128,256] @ V[256,64] ----
    const int wm2 = w & 3, wn2 = w >> 2;
    float acc2[2][4][4];
    #pragma unroll
    for (int im = 0; im < 2; im++)
        #pragma unroll
        for (int in = 0; in < 4; in++)
            #pragma unroll
            for (int r = 0; r < 4; r++) acc2[im][in][r] = 0.f;

    #pragma unroll 4
    for (int ks = 0; ks < 16; ks++) {
        uint32_t aH[2][4], aL[2][4], bH[4][2], bL[4][2];
        #pragma unroll
        for (int im = 0; im < 2; im++) {
            int r = wm2 * 32 + im * 16 + a_r;
            int cc = ks * 2 + a_c;
            uint32_t ad = r * 512 + (((cc) ^ (r & 7)) << 4);
            LDSM4(aH[im], S0 + ad);
            LDSM4(aL[im], S1 + ad);
        }
        #pragma unroll
        for (int g = 0; g < 2; g++) {
            int n0 = wn2 * 32 + g * 16;
            int kr = ks * 16 + ((lane >> 3) & 1) * 8 + (lane & 7);
            int cn = (n0 >> 3) + (lane >> 4);
            uint32_t bd = KH + kr * 128 + ((cn ^ (kr & 7)) << 4);
            uint32_t t4[4];
            LDSM4T(t4, bd);
            bH[g*2][0] = t4[0]; bH[g*2][1] = t4[1]; bH[g*2+1][0] = t4[2]; bH[g*2+1][1] = t4[3];
            LDSM4T(t4, bd + 32768);
            bL[g*2][0] = t4[0]; bL[g*2][1] = t4[1]; bL[g*2+1][0] = t4[2]; bL[g*2+1][1] = t4[3];
        }
        #pragma unroll
        for (int im = 0; im < 2; im++)
            #pragma unroll
            for (int in = 0; in < 4; in++) {
                MMA_BF16(acc2[im][in], aH[im], bH[in]);
                MMA_BF16(acc2[im][in], aH[im], bL[in]);
                MMA_BF16(acc2[im][in], aL[im], bH[in]);
            }
    }

    // epilogue: write O hi/lo
    #pragma unroll
    for (int im = 0; im < 2; im++) {
        int rloc = wm2 * 32 + im * 16 + (lane >> 2);
        size_t t0 = (tok0 + qt * 128 + rloc) * EDIM;
        size_t t1 = (tok0 + qt * 128 + rloc + 8) * EDIM;
        #pragma unroll
        for (int in = 0; in < 4; in++) {
            int c = h * HDIM + wn2 * 32 + in * 8 + (lane & 3) * 2;
            union { __nv_bfloat16 b[2]; uint32_t u; } h0, l0, h1, l1;
            split_bf16(acc2[im][in][0], h0.b[0], l0.b[0]);
            split_bf16(acc2[im][in][1], h0.b[1], l0.b[1]);
            split_bf16(acc2[im][in][2], h1.b[0], l1.b[0]);
            split_bf16(acc2[im][in][3], h1.b[1], l1.b[1]);
            *(uint32_t*)(Oh + t0 + c) = h0.u;
            *(uint32_t*)(Ol + t0 + c) = l0.u;
            *(uint32_t*)(Oh + t1 + c) = h1.u;
            *(uint32_t*)(Ol + t1 + c) = l1.u;
        }
    }
}

// -------------------- cosine --------------------
__global__ void __launch_bounds__(256) cos_kernel(
    const float* __restrict__ tok, const float* __restrict__ out, float* __restrict__ cosb)
{
    const int t = blockIdx.x * 8 + (threadIdx.x >> 5);
    const int l = threadIdx.x & 31;
    const float* a = tok + (size_t)t * EDIM;
    const float* b = out + (size_t)t * EDIM;
    float dot = 0.f, na = 0.f, nb = 0.f;
    for (int i = l; i < EDIM; i += 32) {
        float x = a[i], y = b[i];
        dot += x * y; na += x * x; nb += y * y;
    }
    #pragma unroll
    for (int o = 16; o > 0; o >>= 1) {
        dot += __shfl_xor_sync(0xffffffffu, dot, o);
        na  += __shfl_xor_sync(0xffffffffu, na,  o);
        nb  += __shfl_xor_sync(0xffffffffu, nb,  o);
    }
    if (l == 0)
        cosb[t] = dot / fmaxf(sqrtf(na) * sqrtf(nb), 1e-8f);
}

// -------------------- masked softmax + gumbel top-k --------------------
__global__ void __launch_bounds__(256) topk_kernel(
    const float* __restrict__ cosb, const float* __restrict__ gh, const float* __restrict__ gt,
    const int* __restrict__ typ, float* __restrict__ out)
{
    __shared__ float red[8];
    __shared__ float glh[256], glt[256];
    const int b = blockIdx.x, s = threadIdx.x;
    const int idx = b * SEQ + s;
    const int t = typ[idx];
    const float c = cosb[idx];
    const bool vh = (t == 1), vt = (t == 2);
    float eh = vh ? expf(c) : 0.f;
    float et = vt ? expf(c) : 0.f;
    float Zh = block_sum256(eh, red);
    float Zt = block_sum256(et, red);
    glh[s] = vh ? (logf(eh / Zh) + gh[idx]) : -1e30f;
    glt[s] = vt ? (logf(1.0f - et / Zt) + gt[idx]) : -1e30f;
    __syncthreads();
    int ch = 0, ct = 0;
    const float mh = glh[s], mt = glt[s];
    for (int j = 0; j < 256; j++) {
        float a = glh[j], d = glt[j];
        ch += (a > mh) || (a == mh && j < s);
        ct += (d > mt) || (d == mt && j < s);
    }
    float r = 0.f;
    if (vh && ch < 64) r += 1.0f;
    if (vt && ct < 63) r += 1.0f;
    out[idx] = r;
}

// -------------------- host orchestration --------------------
extern "C" void kernel_launch(void* const* d_in, const int* in_sizes, int n_in,
                              void* d_out, int out_size)
{
    const float* tok  = (const float*)d_in[0];
    const int*   pos  = (const int*)  d_in[2];
    const int*   typ  = (const int*)  d_in[3];
    const float* gh   = (const float*)d_in[4];
    const float* gt   = (const float*)d_in[5];
    const float* pe   = (const float*)d_in[6];
    const float* temb = (const float*)d_in[7];
    const float* lnw  = (const float*)d_in[8];
    const float* lnb  = (const float*)d_in[9];
    const float* dw   = (const float*)d_in[10];
    const float* db   = (const float*)d_in[11];
    const float* qkvw = (const float*)d_in[12];
    const float* qkvb = (const float*)d_in[13];
    const float* ow   = (const float*)d_in[14];
    const float* obv  = (const float*)d_in[15];
    const float* ln1w = (const float*)d_in[16];
    const float* ln1b = (const float*)d_in[17];
    const float* l1w  = (const float*)d_in[18];
    const float* l1b  = (const float*)d_in[19];
    const float* l2w  = (const float*)d_in[20];
    const float* l2b  = (const float*)d_in[21];
    const float* ln2w = (const float*)d_in[22];
    const float* ln2b = (const float*)d_in[23];

    float *X, *Y, *O, *C;
    __nv_bfloat16 *Ah, *Al, *Fh, *Fl, *QKVh, *QKVl;
    __nv_bfloat16 *Wqh, *Wql, *Woh, *Wol, *W1h, *W1l, *W2h, *W2l, *Wdh, *Wdl;
    cudaGetSymbolAddress((void**)&X,    g_X);
    cudaGetSymbolAddress((void**)&Y,    g_Yb);
    cudaGetSymbolAddress((void**)&O,    g_O);
    cudaGetSymbolAddress((void**)&C,    g_C);
    cudaGetSymbolAddress((void**)&Ah,   g_Ah);
    cudaGetSymbolAddress((void**)&Al,   g_Al);
    cudaGetSymbolAddress((void**)&Fh,   g_Fh);
    cudaGetSymbolAddress((void**)&Fl,   g_Fl);
    cudaGetSymbolAddress((void**)&QKVh, g_QKVh);
    cudaGetSymbolAddress((void**)&QKVl, g_QKVl);
    cudaGetSymbolAddress((void**)&Wqh, g_Wqkv_h); cudaGetSymbolAddress((void**)&Wql, g_Wqkv_l);
    cudaGetSymbolAddress((void**)&Woh, g_Wout_h); cudaGetSymbolAddress((void**)&Wol, g_Wout_l);
    cudaGetSymbolAddress((void**)&W1h, g_W1_h);   cudaGetSymbolAddress((void**)&W1l, g_W1_l);
    cudaGetSymbolAddress((void**)&W2h, g_W2_h);   cudaGetSymbolAddress((void**)&W2l, g_W2_l);
    cudaGetSymbolAddress((void**)&Wdh, g_Wd_h);   cudaGetSymbolAddress((void**)&Wdl, g_Wd_l);

    cudaFuncSetAttribute(attn_mma_kernel, cudaFuncAttributeMaxDynamicSharedMemorySize, ATTN_SMEM2);
    cudaFuncSetAttribute(tgemm_kernel<0,0>, cudaFuncAttributeMaxDynamicSharedMemorySize, TG_SMEM);
    cudaFuncSetAttribute(tgemm_kernel<0,1>, cudaFuncAttributeMaxDynamicSharedMemorySize, TG_SMEM);
    cudaFuncSetAttribute(tgemm_kernel<1,1>, cudaFuncAttributeMaxDynamicSharedMemorySize, TG_SMEM);
    cudaFuncSetAttribute(tgemm_kernel<2,0>, cudaFuncAttributeMaxDynamicSharedMemorySize, TG_SMEM);

    // weight conversions
    cvt_kernel<<<1024, 256>>>(qkvw, Wqh, Wql, 2 * E3 * EDIM / 4);
    cvt_kernel<<<1024, 256>>>(ow,   Woh, Wol, 2 * EDIM * EDIM / 4);
    cvt_kernel<<<1024, 256>>>(l1w,  W1h, W1l, 2 * FFDIM * EDIM / 4);
    cvt_kernel<<<1024, 256>>>(l2w,  W2h, W2l, 2 * EDIM * FFDIM / 4);
    cvt_kernel<<<1024, 256>>>(dw,   Wdh, Wdl, EDIM * EDIM / 4);

    embed_ln_kernel<<<NTOK, 256>>>(tok, pos, typ, pe, temb, lnw, lnb, X, Ah, Al);

    for (int l = 0; l < 2; l++) {
        tgemm_kernel<0,1><<<dim3(E3 / 128, NTOK / 128), 256, TG_SMEM>>>(
            Ah, Al, Wqh + (size_t)l * E3 * EDIM, Wql + (size_t)l * E3 * EDIM,
            qkvb + (size_t)l * E3, nullptr, QKVh, QKVl, NTOK, E3, EDIM);
        attn_mma_kernel<<<dim3(2, NB * NH), 256, ATTN_SMEM2>>>(QKVh, QKVl, Ah, Al);
        tgemm_kernel<0,0><<<dim3(EDIM / 128, NTOK / 128), 256, TG_SMEM>>>(
            Ah, Al, Woh + (size_t)l * EDIM * EDIM, Wol + (size_t)l * EDIM * EDIM,
            obv + (size_t)l * EDIM, Y, nullptr, nullptr, NTOK, EDIM, EDIM);
        addln_kernel<true><<<NTOK, 256>>>(X, Y, ln1w + (size_t)l * EDIM, ln1b + (size_t)l * EDIM, X, Ah, Al);
        tgemm_kernel<1,1><<<dim3(FFDIM / 128, NTOK / 128), 256, TG_SMEM>>>(
            Ah, Al, W1h + (size_t)l * FFDIM * EDIM, W1l + (size_t)l * FFDIM * EDIM,
            l1b + (size_t)l * FFDIM, nullptr, Fh, Fl, NTOK, FFDIM, EDIM);
        tgemm_kernel<0,0><<<dim3(EDIM / 128, NTOK / 128), 256, TG_SMEM>>>(
            Fh, Fl, W2h + (size_t)l * EDIM * FFDIM, W2l + (size_t)l * EDIM * FFDIM,
            l2b + (size_t)l * EDIM, Y, nullptr, nullptr, NTOK, EDIM, FFDIM);
        addln_kernel<true><<<NTOK, 256>>>(X, Y, ln2w + (size_t)l * EDIM, ln2b + (size_t)l * EDIM, X, Ah, Al);
    }

    addln_kernel<false><<<NTOK, 256>>>(X, nullptr, lnw, lnb, Y, Ah, Al);
    tgemm_kernel<2,0><<<dim3(EDIM / 128, NTOK / 128), 256, TG_SMEM>>>(
        Ah, Al, Wdh, Wdl, db, O, nullptr, nullptr, NTOK, EDIM, EDIM);
    cos_kernel<<<NTOK / 8, 256>>>(tok, O, C);
    topk_kernel<<<NB, 256>>>(C, gh, gt, typ, (float*)d_out);
}